// round 4
// baseline (speedup 1.0000x reference)
#include <cuda_runtime.h>
#include <cuda_bf16.h>
#include <math.h>

// Problem constants
#define BSZ   8
#define MROW  64
#define NCOL  4096
#define KSEL  32
#define NPAIR (BSZ * MROW)        // 512 (b,m) pairs
#define NROWS (NPAIR * KSEL)      // 16384 output rows
#define TPB   256                 // 8 warps (thresh/fill)
#define VPT   16                  // values/thread in thresh (512 per warp)
#define CAP   NCOL                // candidate cap per row (trivially safe)

// Noise bounds: gn = -0.001*log(-log(u+1e-20)+1e-20)
//   max = -0.001*log(1e-20)   = +0.046052
//   min = -0.001*log(46.052+) = -0.003830
// span < 0.04989 -> margin 0.06 is strictly safe.
#define MARGIN 0.06f

// Static scratch (no allocation allowed)
__device__ int2 g_cand[MROW * CAP];   // (idx, float-bits of logit)
__device__ int  g_cnt[MROW];
__device__ int  g_idx[NROWS];

// Order-preserving float->uint map: a > b  <=>  fmap(a) > fmap(b)
__device__ __forceinline__ unsigned fmap(float f) {
    unsigned b = __float_as_uint(f);
    return b ^ ((unsigned)(((int)b) >> 31) | 0x80000000u);
}
__device__ __forceinline__ float unfmap(unsigned m) {
    unsigned b = (m & 0x80000000u) ? (m ^ 0x80000000u) : ~m;
    return __uint_as_float(b);
}

// ---------------------------------------------------------------------------
// Kernel 1: per logit row, find 32nd-largest logit, compact candidates.
// 64 blocks x 256 threads. No MUFU.
// ---------------------------------------------------------------------------
__global__ __launch_bounds__(TPB)
void thresh_kernel(const float* __restrict__ logits)
{
    const int m    = blockIdx.x;            // 0..63
    const int t    = threadIdx.x;
    const int lane = t & 31;
    const int warp = t >> 5;

    __shared__ unsigned s_cval[TPB];        // 8 warps x 32 local top values
    __shared__ unsigned s_tm;               // mapped 32nd-largest logit
    __shared__ int      s_cnt;

    const int base = warp * 512 + lane * VPT;
    const float4* __restrict__ l4 = (const float4*)(logits + (size_t)m * NCOL);
    const int p = base >> 2;

    float    f[VPT];                         // pristine logits
    unsigned um[VPT];                        // working mapped copy
#pragma unroll
    for (int q = 0; q < 4; q++) {
        float4 ll = l4[p + q];
        f[q*4+0] = ll.x; f[q*4+1] = ll.y; f[q*4+2] = ll.z; f[q*4+3] = ll.w;
    }
#pragma unroll
    for (int j = 0; j < VPT; j++) um[j] = fmap(f[j]);

    const unsigned FULL = 0xffffffffu;

    // Phase 1: each warp extracts its top-32 values (multiset semantics).
    for (int it = 0; it < KSEL; it++) {
        unsigned lm = um[0];
#pragma unroll
        for (int j = 1; j < VPT; j++) lm = max(lm, um[j]);
        const unsigned w = __reduce_max_sync(FULL, lm);

        int myj = VPT;
#pragma unroll
        for (int j = VPT - 1; j >= 0; j--) if (um[j] == w) myj = j;

        const unsigned bal = __ballot_sync(FULL, myj < VPT);
        const int src = __ffs(bal) - 1;
        if (lane == 0) s_cval[warp * KSEL + it] = w;
        if (lane == src) {
#pragma unroll
            for (int j = 0; j < VPT; j++) if (j == myj) um[j] = 0u;
        }
    }
    __syncthreads();

    // Phase 2: warp 0 merges 256 values; the 32nd extraction is the threshold.
    if (warp == 0) {
        unsigned cv[8];
#pragma unroll
        for (int j = 0; j < 8; j++) cv[j] = s_cval[lane * 8 + j];
        for (int it = 0; it < KSEL; it++) {
            unsigned lm = cv[0];
#pragma unroll
            for (int j = 1; j < 8; j++) lm = max(lm, cv[j]);
            const unsigned w = __reduce_max_sync(FULL, lm);
            if (it == KSEL - 1 && lane == 0) s_tm = w;

            int myj = 8;
#pragma unroll
            for (int j = 7; j >= 0; j--) if (cv[j] == w) myj = j;
            const unsigned bal = __ballot_sync(FULL, myj < 8);
            const int src = __ffs(bal) - 1;
            if (lane == src) {
#pragma unroll
                for (int j = 0; j < 8; j++) if (j == myj) cv[j] = 0u;
            }
        }
    }
    if (t == 0) s_cnt = 0;
    __syncthreads();

    // Compact candidates: logit >= T - MARGIN.
    const float thrf = unfmap(s_tm) - MARGIN;
#pragma unroll
    for (int j = 0; j < VPT; j++) {
        if (f[j] >= thrf) {
            const int pos = atomicAdd(&s_cnt, 1);
            g_cand[m * CAP + pos] = make_int2(base + j, __float_as_int(f[j]));
        }
    }
    __syncthreads();
    if (t == 0) g_cnt[m] = s_cnt;
}

// ---------------------------------------------------------------------------
// Kernel 2: per (b,m), exact top-32 over the candidate set (MUFU only here).
// 512 blocks x 32 threads.
// ---------------------------------------------------------------------------
__global__ __launch_bounds__(32)
void select_kernel(const float* __restrict__ u)
{
    const int bm   = blockIdx.x;            // 0..511
    const int m    = bm & (MROW - 1);
    const int lane = threadIdx.x;
    const int cnt  = g_cnt[m];              // >= 32 by construction

    __shared__ unsigned long long s_keys[CAP];   // 32 KB
    __shared__ int s_sel[KSEL];

    const float* __restrict__ urow = u + (size_t)bm * NCOL;
    for (int i = lane; i < cnt; i += 32) {
        const int2 c = g_cand[m * CAP + i];
        const float uu = urow[c.x];
        const float gn = -0.001f * __logf(-__logf(uu + 1e-20f) + 1e-20f);
        const float val = __int_as_float(c.y) + gn;
        // unique key; larger value wins, ties -> lower index (via ~idx)
        s_keys[i] = ((unsigned long long)fmap(val) << 32) | (unsigned)(~c.x);
    }
    __syncwarp();

    const unsigned FULL = 0xffffffffu;
    for (int it = 0; it < KSEL; it++) {
        unsigned long long best = 0ull;
        int bpos = -1;
        for (int i = lane; i < cnt; i += 32) {
            const unsigned long long k = s_keys[i];
            if (k > best) { best = k; bpos = i; }
        }
        unsigned long long w = best;
#pragma unroll
        for (int off = 16; off > 0; off >>= 1) {
            const unsigned long long o = __shfl_xor_sync(FULL, w, off);
            if (o > w) w = o;
        }
        if (lane == 0) s_sel[it] = (int)(~(unsigned)w);     // low 32 bits -> idx
        const unsigned bal = __ballot_sync(FULL, best == w); // exactly one lane
        const int src = __ffs(bal) - 1;
        if (lane == src) s_keys[bpos] = 0ull;
        __syncwarp();
    }

    // rank-by-counting -> ascending-sorted indices (all distinct)
    const int myidx = s_sel[lane];
    int rank = 0;
#pragma unroll
    for (int j = 0; j < KSEL; j++) rank += (s_sel[j] < myidx) ? 1 : 0;
    g_idx[bm * KSEL + rank] = myidx;
}

// ---------------------------------------------------------------------------
// Kernel 3: one block per output row, fused memset + one-hot scatter.
// ---------------------------------------------------------------------------
__global__ __launch_bounds__(TPB)
void fill_kernel(float* __restrict__ out)
{
    const int r = blockIdx.x;                 // 0..NROWS-1
    const int target = g_idx[r];
    float4* __restrict__ o = reinterpret_cast<float4*>(out + (size_t)r * NCOL);

    const int t = threadIdx.x;
#pragma unroll
    for (int i = 0; i < 4; i++) {
        const int slot = t + i * TPB;         // float4 slot 0..1023
        const int n0 = slot * 4;
        float4 val;
        val.x = (target == n0    ) ? 1.0f : 0.0f;
        val.y = (target == n0 + 1) ? 1.0f : 0.0f;
        val.z = (target == n0 + 2) ? 1.0f : 0.0f;
        val.w = (target == n0 + 3) ? 1.0f : 0.0f;
        o[slot] = val;
    }
}

extern "C" void kernel_launch(void* const* d_in, const int* in_sizes, int n_in,
                              void* d_out, int out_size)
{
    const float* logits = (const float*)d_in[0];   // (64, 4096) fp32
    const float* u      = (const float*)d_in[1];   // (8, 64, 4096) fp32
    float*       out    = (float*)d_out;           // (8, 64, 32, 4096) fp32

    thresh_kernel<<<MROW, TPB>>>(logits);
    select_kernel<<<NPAIR, 32>>>(u);
    fill_kernel<<<NROWS, TPB>>>(out);
}

// round 5
// speedup vs baseline: 1.0302x; 1.0302x over previous
#include <cuda_runtime.h>
#include <cuda_bf16.h>
#include <math.h>

// Problem constants
#define BSZ   8
#define MROW  64
#define NCOL  4096
#define KSEL  32
#define NPAIR (BSZ * MROW)        // 512 (b,m) pairs
#define NROWS (NPAIR * KSEL)      // 16384 output rows
#define TPB   256                 // 8 warps
#define VPT   16                  // logits per thread (4096/256)
#define NBKT  4096                // histogram buckets (top 12 bits of fmap)
#define CAP   2048                // candidate cap (expected ~75)

// Noise bounds: gn = -0.001*log(-log(u+1e-20)+1e-20) in [-0.003830, +0.046052],
// span < 0.04989 -> margin 0.06 is strictly safe.
#define MARGIN 0.06f

// Static scratch (no allocation allowed)
__device__ int g_idx[NROWS];

// Order-preserving float->uint map: a > b  <=>  fmap(a) > fmap(b)
__device__ __forceinline__ unsigned fmap(float f) {
    unsigned b = __float_as_uint(f);
    return b ^ ((unsigned)(((int)b) >> 31) | 0x80000000u);
}
__device__ __forceinline__ float unfmap(unsigned m) {
    unsigned b = (m & 0x80000000u) ? (m ^ 0x80000000u) : ~m;
    return __uint_as_float(b);
}

// ---------------------------------------------------------------------------
// Fused kernel: per (b,m) pair -> histogram threshold -> candidate gather ->
// exact top-32 -> ascending-sorted indices into g_idx.
// 512 blocks x 256 threads.
// ---------------------------------------------------------------------------
__global__ __launch_bounds__(TPB)
void select_kernel(const float* __restrict__ logits, const float* __restrict__ u)
{
    const int bm   = blockIdx.x;            // 0..511
    const int m    = bm & (MROW - 1);
    const int t    = threadIdx.x;
    const int lane = t & 31;
    const int warp = t >> 5;

    __shared__ int                s_hist[NBKT];      // 16 KB
    __shared__ unsigned long long s_keys[CAP];       // 16 KB
    __shared__ int                s_sel[KSEL];
    __shared__ int                s_cnt;
    __shared__ int                s_bkt;

    // ---- Load logits row into registers (L2-hot: 64 distinct rows) ----
    const int base = t * VPT;
    const float4* __restrict__ l4 = (const float4*)(logits + (size_t)m * NCOL);
    float f[VPT];
#pragma unroll
    for (int q = 0; q < 4; q++) {
        float4 ll = l4[(base >> 2) + q];
        f[q*4+0] = ll.x; f[q*4+1] = ll.y; f[q*4+2] = ll.z; f[q*4+3] = ll.w;
    }

    // ---- Histogram of fmap top-12 bits ----
#pragma unroll
    for (int i = 0; i < NBKT / TPB; i++) s_hist[t + i * TPB] = 0;
    if (t == 0) s_cnt = 0;
    __syncthreads();
#pragma unroll
    for (int j = 0; j < VPT; j++)
        atomicAdd(&s_hist[fmap(f[j]) >> 20], 1);
    __syncthreads();

    // ---- Warp 0: scan from top to find bucket holding the 32nd-largest ----
    if (warp == 0) {
        const unsigned FULL = 0xffffffffu;
        int cum = 0;
        for (int bb = NBKT - 32; bb >= 0; bb -= 32) {
            const int c = s_hist[bb + lane];
            // inclusive suffix sum over lanes (lane i gets sum of lanes >= i)
            int suf = c;
#pragma unroll
            for (int off = 1; off < 32; off <<= 1) {
                const int o = __shfl_down_sync(FULL, suf, off);
                if (lane + off < 32) suf += o;
            }
            const int total = __shfl_sync(FULL, suf, 0);
            if (cum + total >= KSEL) {
                // highest lane with cum + suffix >= KSEL
                const unsigned bal = __ballot_sync(FULL, cum + suf >= KSEL);
                const int hi = 31 - __clz(bal);
                if (lane == 0) s_bkt = bb + hi;
                break;
            }
            cum += total;
        }
    }
    __syncthreads();

    // ---- Candidate gather: logit >= bucket_edge - MARGIN ----
    const float thrf = unfmap((unsigned)s_bkt << 20) - MARGIN;
    const float* __restrict__ urow = u + (size_t)bm * NCOL;
#pragma unroll
    for (int j = 0; j < VPT; j++) {
        if (f[j] >= thrf) {
            const int pos = atomicAdd(&s_cnt, 1);
            if (pos < CAP) {
                const int idx = base + j;
                const float uu = urow[idx];
                const float gn = -0.001f * __logf(-__logf(uu + 1e-20f) + 1e-20f);
                const float val = f[j] + gn;
                // unique key; larger value wins, ties -> lower index (via ~idx)
                s_keys[pos] = ((unsigned long long)fmap(val) << 32) | (unsigned)(~idx);
            }
        }
    }
    __syncthreads();

    // ---- Warp 0: exact top-32 over candidates, then rank-sort ----
    if (warp == 0) {
        const unsigned FULL = 0xffffffffu;
        const int cnt = min(s_cnt, CAP);    // >= KSEL by threshold construction
        for (int it = 0; it < KSEL; it++) {
            unsigned long long best = 0ull;
            int bpos = -1;
            for (int i = lane; i < cnt; i += 32) {
                const unsigned long long k = s_keys[i];
                if (k > best) { best = k; bpos = i; }
            }
            unsigned long long w = best;
#pragma unroll
            for (int off = 16; off > 0; off >>= 1) {
                const unsigned long long o = __shfl_xor_sync(FULL, w, off);
                if (o > w) w = o;
            }
            if (lane == 0) s_sel[it] = (int)(~(unsigned)w);
            const unsigned bal = __ballot_sync(FULL, best == w);  // exactly one lane
            const int src = __ffs(bal) - 1;
            if (lane == src) s_keys[bpos] = 0ull;
            __syncwarp();
        }
        // rank-by-counting -> ascending-sorted (all indices distinct)
        const int myidx = s_sel[lane];
        int rank = 0;
#pragma unroll
        for (int j = 0; j < KSEL; j++) rank += (s_sel[j] < myidx) ? 1 : 0;
        g_idx[bm * KSEL + rank] = myidx;
    }
}

// ---------------------------------------------------------------------------
// One block per output row: fused memset + one-hot scatter (proven config).
// ---------------------------------------------------------------------------
__global__ __launch_bounds__(TPB)
void fill_kernel(float* __restrict__ out)
{
    const int r = blockIdx.x;                 // 0..NROWS-1
    const int target = g_idx[r];
    float4* __restrict__ o = reinterpret_cast<float4*>(out + (size_t)r * NCOL);

    const int t = threadIdx.x;
#pragma unroll
    for (int i = 0; i < 4; i++) {
        const int slot = t + i * TPB;         // float4 slot 0..1023
        const int n0 = slot * 4;
        float4 val;
        val.x = (target == n0    ) ? 1.0f : 0.0f;
        val.y = (target == n0 + 1) ? 1.0f : 0.0f;
        val.z = (target == n0 + 2) ? 1.0f : 0.0f;
        val.w = (target == n0 + 3) ? 1.0f : 0.0f;
        o[slot] = val;
    }
}

extern "C" void kernel_launch(void* const* d_in, const int* in_sizes, int n_in,
                              void* d_out, int out_size)
{
    const float* logits = (const float*)d_in[0];   // (64, 4096) fp32
    const float* u      = (const float*)d_in[1];   // (8, 64, 4096) fp32
    float*       out    = (float*)d_out;           // (8, 64, 32, 4096) fp32

    select_kernel<<<NPAIR, TPB>>>(logits, u);
    fill_kernel<<<NROWS, TPB>>>(out);
}

// round 6
// speedup vs baseline: 1.2456x; 1.2090x over previous
#include <cuda_runtime.h>
#include <cuda_bf16.h>
#include <math.h>

// Problem constants
#define BSZ   8
#define MROW  64
#define NCOL  4096
#define KSEL  32
#define NPAIR (BSZ * MROW)        // 512 (b,m) pairs
#define NROWS (NPAIR * KSEL)      // 16384 output rows
#define TPB   256                 // 8 warps
#define VPT   16                  // logits per thread (4096/256)
#define NBKT  4096                // histogram buckets (top 12 bits of fmap)
#define CAP   4096                // absolute candidate cap (overflow impossible)
#define RFAST 256                 // register fast-path candidate limit (8/lane)

// Noise bounds: gn = -0.001*log(-log(u+1e-20)+1e-20) in [-0.003830, +0.046052],
// span < 0.04989 -> margin 0.06 is strictly safe.
#define MARGIN 0.06f

// Static scratch (no allocation allowed)
__device__ int g_idx[NROWS];

// Order-preserving float->uint map: a > b  <=>  fmap(a) > fmap(b)
__device__ __forceinline__ unsigned fmap(float f) {
    unsigned b = __float_as_uint(f);
    return b ^ ((unsigned)(((int)b) >> 31) | 0x80000000u);
}
__device__ __forceinline__ float unfmap(unsigned m) {
    unsigned b = (m & 0x80000000u) ? (m ^ 0x80000000u) : ~m;
    return __uint_as_float(b);
}

// ---------------------------------------------------------------------------
// Fused select: per (b,m) -> histogram threshold -> candidate gather (MUFU only
// on ~50 elements) -> exact top-32 -> ascending-sorted indices into g_idx.
// 512 blocks x 256 threads.
// ---------------------------------------------------------------------------
__global__ __launch_bounds__(TPB)
void select_kernel(const float* __restrict__ logits, const float* __restrict__ u)
{
    const int bm   = blockIdx.x;            // 0..511
    const int m    = bm & (MROW - 1);
    const int t    = threadIdx.x;
    const int lane = t & 31;
    const int warp = t >> 5;

    __shared__ int                s_hist[NBKT];   // 16 KB
    __shared__ unsigned long long s_keys[CAP];    // 32 KB
    __shared__ int                s_sel[KSEL];
    __shared__ int                s_cnt;
    __shared__ int                s_bkt;

    // ---- Load logits row into registers (L2-hot: 64 distinct rows) ----
    const int base = t * VPT;
    const float4* __restrict__ l4 = (const float4*)(logits + (size_t)m * NCOL);
    float f[VPT];
#pragma unroll
    for (int q = 0; q < 4; q++) {
        float4 ll = l4[(base >> 2) + q];
        f[q*4+0] = ll.x; f[q*4+1] = ll.y; f[q*4+2] = ll.z; f[q*4+3] = ll.w;
    }

    // ---- Histogram of fmap top-12 bits ----
#pragma unroll
    for (int i = 0; i < NBKT / (TPB * 4); i++)
        ((int4*)s_hist)[t + i * TPB] = make_int4(0, 0, 0, 0);
    if (t == 0) s_cnt = 0;
    __syncthreads();
#pragma unroll
    for (int j = 0; j < VPT; j++)
        atomicAdd(&s_hist[fmap(f[j]) >> 20], 1);
    __syncthreads();

    // ---- Warp 0: scan 64-bucket chunks from the top; cheap REDUX totals,
    //      full suffix-scan only inside the single crossing chunk. ----
    if (warp == 0) {
        const unsigned FULL = 0xffffffffu;
        int cum = 0;
        for (int bb = NBKT - 64; bb >= 0; bb -= 64) {
            const int2 c = ((const int2*)(s_hist + bb))[lane];   // 2 buckets/lane
            const int pair  = c.x + c.y;
            const int total = __reduce_add_sync(FULL, pair);
            if (cum + total >= KSEL) {
                // inclusive suffix sum over lanes (lane i: sum of lanes >= i)
                int suf = pair;
#pragma unroll
                for (int off = 1; off < 32; off <<= 1) {
                    const int o = __shfl_down_sync(FULL, suf, off);
                    if (lane + off < 32) suf += o;
                }
                const int cx = cum + suf;          // cumulative incl. this lane's 2 buckets
                const unsigned bal = __ballot_sync(FULL, cx >= KSEL);
                const int hi = 31 - __clz(bal);    // highest such lane
                if (lane == hi) {
                    const int cy = cx - c.x;       // cumulative incl. upper bucket only
                    s_bkt = bb + lane * 2 + ((cy >= KSEL) ? 1 : 0);
                }
                break;
            }
            cum += total;
        }
    }
    __syncthreads();

    // ---- Candidate gather: logit >= bucket_edge - MARGIN; noise only here ----
    const float thrf = unfmap((unsigned)s_bkt << 20) - MARGIN;
    const float* __restrict__ urow = u + (size_t)bm * NCOL;
#pragma unroll
    for (int j = 0; j < VPT; j++) {
        if (f[j] >= thrf) {
            const int pos = atomicAdd(&s_cnt, 1);  // pos < CAP always (CAP = NCOL)
            const int idx = base + j;
            const float uu = urow[idx];
            const float gn = -0.001f * __logf(-__logf(uu + 1e-20f) + 1e-20f);
            const float val = f[j] + gn;
            // unique key; larger value wins, ties -> lower index (via ~idx)
            s_keys[pos] = ((unsigned long long)fmap(val) << 32) | (unsigned)(~idx);
        }
    }
    __syncthreads();

    // ---- Warp 0: exact top-32 via double 32-bit REDUX, then rank-sort ----
    if (warp == 0) {
        const unsigned FULL = 0xffffffffu;
        const int cnt = s_cnt;                     // >= KSEL by construction

        if (cnt <= RFAST) {
            // register fast path: 8 candidates per lane
            unsigned long long kk[8];
#pragma unroll
            for (int j = 0; j < 8; j++) {
                const int i = j * 32 + lane;
                kk[j] = (i < cnt) ? s_keys[i] : 0ull;
            }
            for (int it = 0; it < KSEL; it++) {
                unsigned long long b = kk[0];
                int bj = 0;
#pragma unroll
                for (int j = 1; j < 8; j++) if (kk[j] > b) { b = kk[j]; bj = j; }
                const unsigned hi = (unsigned)(b >> 32);
                const unsigned wh = __reduce_max_sync(FULL, hi);
                const unsigned lo = (hi == wh) ? (unsigned)b : 0u;
                const unsigned wl = __reduce_max_sync(FULL, lo);
                if (hi == wh && (unsigned)b == wl) {   // unique owner
#pragma unroll
                    for (int j = 0; j < 8; j++) if (j == bj) kk[j] = 0ull;
                }
                if (lane == 0) s_sel[it] = (int)(~wl);
            }
        } else {
            // smem fallback (correct for any cnt <= CAP; never taken for this data)
            for (int it = 0; it < KSEL; it++) {
                unsigned long long b = 0ull;
                int bpos = -1;
                for (int i = lane; i < cnt; i += 32) {
                    const unsigned long long k = s_keys[i];
                    if (k > b) { b = k; bpos = i; }
                }
                const unsigned hi = (unsigned)(b >> 32);
                const unsigned wh = __reduce_max_sync(FULL, hi);
                const unsigned lo = (hi == wh) ? (unsigned)b : 0u;
                const unsigned wl = __reduce_max_sync(FULL, lo);
                if (hi == wh && (unsigned)b == wl) s_keys[bpos] = 0ull;
                __syncwarp();
                if (lane == 0) s_sel[it] = (int)(~wl);
            }
        }
        __syncwarp();
        // rank-by-counting -> ascending-sorted (all indices distinct)
        const int myidx = s_sel[lane];
        int rank = 0;
#pragma unroll
        for (int j = 0; j < KSEL; j++) rank += (s_sel[j] < myidx) ? 1 : 0;
        g_idx[bm * KSEL + rank] = myidx;
    }
}

// ---------------------------------------------------------------------------
// One block per output row: fused memset + one-hot scatter (proven config).
// ---------------------------------------------------------------------------
__global__ __launch_bounds__(TPB)
void fill_kernel(float* __restrict__ out)
{
    const int r = blockIdx.x;                 // 0..NROWS-1
    const int target = g_idx[r];
    float4* __restrict__ o = reinterpret_cast<float4*>(out + (size_t)r * NCOL);

    const int t = threadIdx.x;
#pragma unroll
    for (int i = 0; i < 4; i++) {
        const int slot = t + i * TPB;         // float4 slot 0..1023
        const int n0 = slot * 4;
        float4 val;
        val.x = (target == n0    ) ? 1.0f : 0.0f;
        val.y = (target == n0 + 1) ? 1.0f : 0.0f;
        val.z = (target == n0 + 2) ? 1.0f : 0.0f;
        val.w = (target == n0 + 3) ? 1.0f : 0.0f;
        o[slot] = val;
    }
}

extern "C" void kernel_launch(void* const* d_in, const int* in_sizes, int n_in,
                              void* d_out, int out_size)
{
    const float* logits = (const float*)d_in[0];   // (64, 4096) fp32
    const float* u      = (const float*)d_in[1];   // (8, 64, 4096) fp32
    float*       out    = (float*)d_out;           // (8, 64, 32, 4096) fp32

    select_kernel<<<NPAIR, TPB>>>(logits, u);
    fill_kernel<<<NROWS, TPB>>>(out);
}

// round 7
// speedup vs baseline: 1.4579x; 1.1705x over previous
#include <cuda_runtime.h>
#include <cuda_bf16.h>
#include <math.h>

// Problem constants
#define BSZ   8
#define MROW  64
#define NCOL  4096
#define KSEL  32
#define NPAIR (BSZ * MROW)        // 512 (b,m) pairs
#define NROWS (NPAIR * KSEL)      // 16384 output rows
#define TPB   256                 // 8 warps
#define VPT   16                  // logits per thread (4096/256)
#define NBKT  4096                // histogram buckets (top 12 bits of fmap)
#define CAP   2048                // candidate cap (expected ~50-100)

// Noise bounds: gn = -0.001*log(-log(u+1e-20)+1e-20) in [-0.003830, +0.046052],
// span < 0.04989 -> margin 0.06 is strictly safe.
#define MARGIN 0.06f

// Static scratch (no allocation allowed)
__device__ int g_idx[NROWS];

// Order-preserving float->uint map: a > b  <=>  fmap(a) > fmap(b). Bijective.
__device__ __forceinline__ unsigned fmap(float f) {
    unsigned b = __float_as_uint(f);
    return b ^ ((unsigned)(((int)b) >> 31) | 0x80000000u);
}
__device__ __forceinline__ float unfmap(unsigned m) {
    unsigned b = (m & 0x80000000u) ? (m ^ 0x80000000u) : ~m;
    return __uint_as_float(b);
}

// ---------------------------------------------------------------------------
// Fused select: per (b,m) -> top-4 prefilter -> filtered histogram threshold
// -> candidate keys (noise only on ~4/thread, prefetched) -> parallel
// rank-count top-32 -> ascending-sorted indices into g_idx.
// 512 blocks x 256 threads.
// ---------------------------------------------------------------------------
__global__ __launch_bounds__(TPB)
void select_kernel(const float* __restrict__ logits, const float* __restrict__ u)
{
    const int bm   = blockIdx.x;            // 0..511
    const int m    = bm & (MROW - 1);
    const int t    = threadIdx.x;
    const int lane = t & 31;
    const int warp = t >> 5;

    __shared__ int                s_hist[NBKT];   // 16 KB
    __shared__ unsigned long long s_keys[CAP];    // 16 KB
    __shared__ int                s_top[KSEL];
    __shared__ int                s_cnt;
    __shared__ int                s_bkt;

    // ---- Load logits row into registers (L2-hot: 64 distinct rows) ----
    const int base = t * VPT;
    const float4* __restrict__ l4 = (const float4*)(logits + (size_t)m * NCOL);
    float f[VPT];
#pragma unroll
    for (int q = 0; q < 4; q++) {
        float4 ll = l4[(base >> 2) + q];
        f[q*4+0] = ll.x; f[q*4+1] = ll.y; f[q*4+2] = ll.z; f[q*4+3] = ll.w;
    }

    // ---- Zero histogram (before using it) ----
#pragma unroll
    for (int i = 0; i < NBKT / (TPB * 4); i++)
        ((int4*)s_hist)[t + i * TPB] = make_int4(0, 0, 0, 0);
    if (t == 0) s_cnt = 0;

    // ---- Per-thread top-4 prefilter (mapped-uint domain, predicated clears) --
    unsigned um[VPT];
#pragma unroll
    for (int j = 0; j < VPT; j++) um[j] = fmap(f[j]);

    int      tj[4];        // local slots of top-4
    unsigned tmu[4];       // their mapped values
#pragma unroll
    for (int p = 0; p < 4; p++) {
        unsigned bv = um[0];
        int bj = 0;
#pragma unroll
        for (int j = 1; j < VPT; j++) if (um[j] > bv) { bv = um[j]; bj = j; }
        tj[p] = bj; tmu[p] = bv;
#pragma unroll
        for (int j = 0; j < VPT; j++) if (j == bj) um[j] = 0u;
    }

    // ---- Prefetch u for the 4 local-top candidates (hides LDG latency) ----
    const float* __restrict__ urow = u + (size_t)bm * NCOL;
    float uu[4];
#pragma unroll
    for (int p = 0; p < 4; p++) uu[p] = urow[base + tj[p]];

    __syncthreads();   // hist zeroed

    // ---- Filtered histogram: 4 atomics/thread (under-count is conservative) --
#pragma unroll
    for (int p = 0; p < 4; p++)
        atomicAdd(&s_hist[tmu[p] >> 20], 1);
    __syncthreads();

    // ---- Warp 0: chunk scan for the bucket where filtered-cum reaches 32 ----
    if (warp == 0) {
        const unsigned FULL = 0xffffffffu;
        int cum = 0;
        for (int bb = NBKT - 64; bb >= 0; bb -= 64) {
            const int2 c = ((const int2*)(s_hist + bb))[lane];   // 2 buckets/lane
            const int pair  = c.x + c.y;
            const int total = __reduce_add_sync(FULL, pair);
            if (cum + total >= KSEL) {
                int suf = pair;   // inclusive suffix sum over lanes
#pragma unroll
                for (int off = 1; off < 32; off <<= 1) {
                    const int o = __shfl_down_sync(FULL, suf, off);
                    if (lane + off < 32) suf += o;
                }
                const int cx = cum + suf;
                const unsigned bal = __ballot_sync(FULL, cx >= KSEL);
                const int hi = 31 - __clz(bal);
                if (lane == hi) {
                    const int cy = cx - c.x;
                    s_bkt = bb + lane * 2 + ((cy >= KSEL) ? 1 : 0);
                }
                break;
            }
            cum += total;
        }
    }

    // ---- All warps: compute keys for prefetched candidates (overlaps scan) --
    unsigned long long pkey[4];
#pragma unroll
    for (int p = 0; p < 4; p++) {
        const float gn  = -0.001f * __logf(-__logf(uu[p] + 1e-20f) + 1e-20f);
        const float val = unfmap(tmu[p]) + gn;
        pkey[p] = ((unsigned long long)fmap(val) << 32)
                | (unsigned)(~(base + tj[p]));
    }
    __syncthreads();   // s_bkt ready

    // ---- Candidate gather: logit >= bucket_edge - MARGIN ----
    const float thrf = unfmap((unsigned)s_bkt << 20) - MARGIN;
    int nq = 0;
#pragma unroll
    for (int j = 0; j < VPT; j++) nq += (f[j] >= thrf) ? 1 : 0;

    if (nq <= 4) {
        // all qualifying values are within local top-4 (prefetched fast path)
#pragma unroll
        for (int p = 0; p < 4; p++) {
            if (unfmap(tmu[p]) >= thrf) {
                const int pos = atomicAdd(&s_cnt, 1);
                if (pos < CAP) s_keys[pos] = pkey[p];
            }
        }
    } else {
        // rare: thread holds >4 qualifying values — exact slow path
#pragma unroll
        for (int j = 0; j < VPT; j++) {
            if (f[j] >= thrf) {
                const int pos = atomicAdd(&s_cnt, 1);
                if (pos < CAP) {
                    const int idx = base + j;
                    const float u2 = urow[idx];
                    const float gn = -0.001f * __logf(-__logf(u2 + 1e-20f) + 1e-20f);
                    const float val = f[j] + gn;
                    s_keys[pos] = ((unsigned long long)fmap(val) << 32)
                                | (unsigned)(~idx);
                }
            }
        }
    }
    __syncthreads();

    // ---- Parallel rank-count top-32 (all 256 threads, broadcast LDS) ----
    const int cnt = min(s_cnt, CAP);           // >= KSEL by construction
    for (int i = t; i < cnt; i += TPB) {
        const unsigned long long k = s_keys[i];
        int r = 0;
        for (int j = 0; j < cnt; j++)
            r += (s_keys[j] > k) ? 1 : 0;      // unique keys -> unique ranks
        if (r < KSEL) s_top[r] = (int)(~(unsigned)k);
    }
    __syncthreads();

    // ---- Index-rank sort of the 32 winners -> ascending order ----
    if (t < KSEL) {
        const int myidx = s_top[t];
        int rank = 0;
#pragma unroll
        for (int j = 0; j < KSEL; j++) rank += (s_top[j] < myidx) ? 1 : 0;
        g_idx[bm * KSEL + rank] = myidx;
    }
}

// ---------------------------------------------------------------------------
// One block per output row: fused memset + one-hot scatter (proven config).
// ---------------------------------------------------------------------------
__global__ __launch_bounds__(TPB)
void fill_kernel(float* __restrict__ out)
{
    const int r = blockIdx.x;                 // 0..NROWS-1
    const int target = g_idx[r];
    float4* __restrict__ o = reinterpret_cast<float4*>(out + (size_t)r * NCOL);

    const int t = threadIdx.x;
#pragma unroll
    for (int i = 0; i < 4; i++) {
        const int slot = t + i * TPB;         // float4 slot 0..1023
        const int n0 = slot * 4;
        float4 val;
        val.x = (target == n0    ) ? 1.0f : 0.0f;
        val.y = (target == n0 + 1) ? 1.0f : 0.0f;
        val.z = (target == n0 + 2) ? 1.0f : 0.0f;
        val.w = (target == n0 + 3) ? 1.0f : 0.0f;
        o[slot] = val;
    }
}

extern "C" void kernel_launch(void* const* d_in, const int* in_sizes, int n_in,
                              void* d_out, int out_size)
{
    const float* logits = (const float*)d_in[0];   // (64, 4096) fp32
    const float* u      = (const float*)d_in[1];   // (8, 64, 4096) fp32
    float*       out    = (float*)d_out;           // (8, 64, 32, 4096) fp32

    select_kernel<<<NPAIR, TPB>>>(logits, u);
    fill_kernel<<<NROWS, TPB>>>(out);
}